// round 10
// baseline (speedup 1.0000x reference)
#include <cuda_runtime.h>

// GRU fused recurrence, fp32 SIMT + packed f32x2 FMA (sm_103a).
// grid = 256 CTAs x 16 batch rows (ONE wave at occ 2); block = 160 threads,
// thread = output column k (k<150). All weights hoisted to registers as packed
// f32x2 feature-pairs (no in-loop LDG). Activations staged in SMEM, read as
// broadcast LDS.128 -> two packed f32x2 operands. Rows accumulated in two
// unrolled 8-row passes to cap accumulator register pressure.
// 2 barriers per step (h-update fused into the hcand threads).
// [R6: identical to R5 — R5 bench died in harness init ("system not yet
//  initialized") before executing; resubmitting for a clean measurement.]

#define TT   128
#define FF   64
#define NU   50
#define K3   150
#define BR   16
#define NTHR 160
#define HP   52   // h row pitch (floats), 16B-aligned rows

typedef unsigned long long u64;

__device__ __forceinline__ void fma2(u64& d, u64 a, u64 b, u64 c) {
    asm("fma.rn.f32x2 %0, %1, %2, %3;" : "=l"(d) : "l"(a), "l"(b), "l"(c));
}
__device__ __forceinline__ u64 pack2(float lo, float hi) {
    u64 r;
    asm("mov.b64 %0, {%1, %2};" : "=l"(r) : "f"(lo), "f"(hi));
    return r;
}
__device__ __forceinline__ float2 unpack2(u64 v) {
    float2 r;
    asm("mov.b64 {%0, %1}, %2;" : "=f"(r.x), "=f"(r.y) : "l"(v));
    return r;
}
__device__ __forceinline__ float sigmoidf_(float v) {
    return __fdividef(1.0f, 1.0f + __expf(-v));
}

__global__ __launch_bounds__(NTHR, 2) void gru_fused_kernel(
    const float* __restrict__ x,    // [4096,128,64]
    const float* __restrict__ W,    // [64,150]
    const float* __restrict__ U,    // [50,150]
    const float* __restrict__ bvec, // [2,150]
    const float* __restrict__ Wd,   // [50,1]
    const float* __restrict__ bd,   // [1]
    float* __restrict__ out)        // [4096,1]
{
    __shared__ __align__(16) float sx[BR * FF];  // [r][f], pitch 64
    __shared__ __align__(16) float sh[BR * HP];  // [r][j], pitch 52
    __shared__ float sgr[BR * NU];               // r-gate exchange
    __shared__ float sz [BR * NU];               // z-gate exchange

    const int tid  = threadIdx.x;
    const int k    = tid;
    const int brow = blockIdx.x * BR;

    for (int i = tid; i < BR * HP; i += NTHR) sh[i] = 0.0f;

    // Weights for this thread's column, packed as f32x2 feature-pairs.
    u64 wp[FF / 2];   // 32 pairs (64 regs)
    u64 up[NU / 2];   // 25 pairs (50 regs)
    u64 bX = 0ull, bH = 0ull;   // biases pre-packed into lane 0
    if (k < K3) {
        bX = pack2(__ldg(&bvec[k]), 0.0f);
        bH = pack2(__ldg(&bvec[K3 + k]), 0.0f);
        #pragma unroll
        for (int fg = 0; fg < FF / 2; fg++)
            wp[fg] = pack2(__ldg(&W[(2 * fg) * K3 + k]),
                           __ldg(&W[(2 * fg + 1) * K3 + k]));
        #pragma unroll
        for (int jg = 0; jg < NU / 2; jg++)
            up[jg] = pack2(__ldg(&U[(2 * jg) * K3 + k]),
                           __ldg(&U[(2 * jg + 1) * K3 + k]));
    }

    // prefetch x tile for t = 0 (BR*FF = 1024 elems, 160 threads -> <=7 each)
    float xr[7];
    #pragma unroll
    for (int i = 0; i < 7; i++) {
        int idx = tid + i * NTHR;
        if (idx < BR * FF) {
            int r = idx >> 6, f = idx & 63;
            xr[i] = __ldg(&x[(size_t)(brow + r) * (TT * FF) + f]);
        }
    }
    __syncthreads();  // h init visible

    #pragma unroll 1
    for (int t = 0; t < TT; t++) {
        // commit prefetched x tile
        #pragma unroll
        for (int i = 0; i < 7; i++) {
            int idx = tid + i * NTHR;
            if (idx < BR * FF) sx[idx] = xr[i];
        }
        __syncthreads();  // (a) sx ready; prev step's sh writes ordered

        // prefetch next step's x
        if (t + 1 < TT) {
            #pragma unroll
            for (int i = 0; i < 7; i++) {
                int idx = tid + i * NTHR;
                if (idx < BR * FF) {
                    int r = idx >> 6, f = idx & 63;
                    xr[i] = __ldg(&x[(size_t)(brow + r) * (TT * FF)
                                     + (size_t)(t + 1) * FF + f]);
                }
            }
        }

        float aX[BR], aH[BR];

        if (k < K3) {
            // two 8-row passes to cap accumulator register pressure
            #pragma unroll
            for (int half = 0; half < 2; half++) {
                const int rb = half * 8;
                u64 accX[8], accH[8];
                #pragma unroll
                for (int r = 0; r < 8; r++) { accX[r] = bX; accH[r] = bH; }

                // xp partial: packed over feature pairs
                #pragma unroll
                for (int fg = 0; fg < FF / 4; fg++) {
                    const int f0 = fg * 4;
                    #pragma unroll
                    for (int r = 0; r < 8; r++) {
                        ulonglong2 xv =
                            *(const ulonglong2*)(sx + (rb + r) * FF + f0);
                        fma2(accX[r], xv.x, wp[2 * fg],     accX[r]);
                        fma2(accX[r], xv.y, wp[2 * fg + 1], accX[r]);
                    }
                }
                // hp partial: 12 quads + tail pair (j = 48,49)
                #pragma unroll
                for (int jg = 0; jg < 12; jg++) {
                    const int j0 = jg * 4;
                    #pragma unroll
                    for (int r = 0; r < 8; r++) {
                        ulonglong2 hv =
                            *(const ulonglong2*)(sh + (rb + r) * HP + j0);
                        fma2(accH[r], hv.x, up[2 * jg],     accH[r]);
                        fma2(accH[r], hv.y, up[2 * jg + 1], accH[r]);
                    }
                }
                #pragma unroll
                for (int r = 0; r < 8; r++) {
                    u64 hv = *(const u64*)(sh + (rb + r) * HP + 48);
                    fma2(accH[r], hv, up[24], accH[r]);
                }
                // finalize lane sums (biases already in lane 0)
                #pragma unroll
                for (int r = 0; r < 8; r++) {
                    float2 px = unpack2(accX[r]);
                    float2 ph = unpack2(accH[r]);
                    aX[rb + r] = px.x + px.y;
                    aH[rb + r] = ph.x + ph.y;
                }
            }
        }

        // gates: k in [0,50) -> z; [50,100) -> r; [100,150) -> hcand + update
        if (k < NU) {
            #pragma unroll
            for (int r = 0; r < BR; r++)
                sz[r * NU + k] = sigmoidf_(aX[r] + aH[r]);
        } else if (k < 2 * NU) {
            const int j = k - NU;
            #pragma unroll
            for (int r = 0; r < BR; r++)
                sgr[r * NU + j] = sigmoidf_(aX[r] + aH[r]);
        }
        __syncthreads();  // (b) sz, sgr ready; all sh reads of this step done

        if (k >= 2 * NU && k < K3) {
            const int j = k - 2 * NU;
            #pragma unroll
            for (int r = 0; r < BR; r++) {
                float hcand = fmaxf(aX[r] + sgr[r * NU + j] * aH[r], 0.0f);
                float zv    = sz[r * NU + j];
                float hold  = sh[r * HP + j];
                sh[r * HP + j] = zv * hold + (1.0f - zv) * hcand;
            }
        }
        // next iteration's barrier (a) orders sh writes before next reads
    }

    __syncthreads();  // final h visible
    if (tid < BR) {
        float acc = bd[0];
        #pragma unroll
        for (int j = 0; j < NU; j++)
            acc += sh[tid * HP + j] * __ldg(&Wd[j]);
        out[brow + tid] = acc;
    }
}

extern "C" void kernel_launch(void* const* d_in, const int* in_sizes, int n_in,
                              void* d_out, int out_size) {
    (void)in_sizes; (void)n_in; (void)out_size;
    const float* x    = (const float*)d_in[0];
    const float* W    = (const float*)d_in[1];
    const float* U    = (const float*)d_in[2];
    const float* bvec = (const float*)d_in[3];
    const float* Wd   = (const float*)d_in[4];
    const float* bd   = (const float*)d_in[5];
    float* out = (float*)d_out;

    gru_fused_kernel<<<4096 / BR, NTHR>>>(x, W, U, bvec, Wd, bd, out);
}

// round 12
// speedup vs baseline: 1.8951x; 1.8951x over previous
#include <cuda_runtime.h>
#include <cstdint>

// GRU split into two kernels (sm_103 base target — no tcgen05 on this toolchain):
//  Phase 1: XP = x.W + b0 for ALL (b,t) via tf32 mma.sync m16n8k8 (feed-forward,
//           non-recurrent; tf32 single-product err ~1e-4, safe vs 1e-3 gate).
//  Phase 2: recurrence hp = h.U + b1 only, fp32 f32x2 SIMT, one wave
//           (grid 256 x 16 rows, 160 thr = column k), XP streamed from DRAM.

#define TT   128
#define FF   64
#define NU   50
#define K3   150
#define XPP  152                   // XP row pitch (floats)
#define BTN  (4096 * 128)          // total bt rows
#define BR   16
#define NTHR 160
#define HP2  52                    // h row pitch
#define NT   19                    // phase-1 n8 tiles (152 cols)

__device__ float g_xp[(size_t)BTN * XPP];   // 319 MB scratch (static device mem)

typedef unsigned long long u64;

__device__ __forceinline__ void fma2(u64& d, u64 a, u64 b, u64 c) {
    asm("fma.rn.f32x2 %0, %1, %2, %3;" : "=l"(d) : "l"(a), "l"(b), "l"(c));
}
__device__ __forceinline__ u64 pack2(float lo, float hi) {
    u64 r; asm("mov.b64 %0, {%1, %2};" : "=l"(r) : "f"(lo), "f"(hi)); return r;
}
__device__ __forceinline__ float2 unpack2(u64 v) {
    float2 r; asm("mov.b64 {%0, %1}, %2;" : "=f"(r.x), "=f"(r.y) : "l"(v)); return r;
}
__device__ __forceinline__ float sigmoidf_(float v) {
    return __fdividef(1.0f, 1.0f + __expf(-v));
}
__device__ __forceinline__ uint32_t f2tf32(float f) {
    uint32_t r; asm("cvt.rna.tf32.f32 %0, %1;" : "=r"(r) : "f"(f)); return r;
}
__device__ __forceinline__ void mma_tf32(float* d, const uint32_t* a,
                                         const uint32_t* b) {
    asm volatile(
        "mma.sync.aligned.m16n8k8.row.col.f32.tf32.tf32.f32 "
        "{%0,%1,%2,%3}, {%4,%5,%6,%7}, {%8,%9}, {%0,%1,%2,%3};"
        : "+f"(d[0]), "+f"(d[1]), "+f"(d[2]), "+f"(d[3])
        : "r"(a[0]), "r"(a[1]), "r"(a[2]), "r"(a[3]), "r"(b[0]), "r"(b[1]));
}

// ---------------- Phase 1: XP[bt][152] = x[bt][64] . W[64][150] + b0 ----------
// grid 4096 (one CTA = one batch row's 128 timesteps), block 128 (4 warps x m32).
__global__ __launch_bounds__(128, 2) void xp_gemm_kernel(
    const float* __restrict__ x,    // [BTN, 64]
    const float* __restrict__ W,    // [64, 150]
    const float* __restrict__ bvec) // [2, 150] (row 0 used here)
{
    __shared__ float sxt[128][68];  // x tile, padded pitch
    const int tid = threadIdx.x, warp = tid >> 5, lane = tid & 31;
    const int g = lane >> 2, tig = lane & 3;
    const size_t btbase = (size_t)blockIdx.x * 128;

    for (int i = tid; i < 128 * FF; i += 128) {
        int r = i >> 6, f = i & 63;
        sxt[r][f] = x[(btbase + r) * FF + f];
    }
    __syncthreads();

    const int mtb = warp * 32;      // warp covers rows [mtb, mtb+32)
    float d[2][NT][4];
    #pragma unroll
    for (int nt = 0; nt < NT; nt++) {          // init D with bias b0
        int c0 = nt * 8 + 2 * tig;
        float bz0 = (c0     < K3) ? __ldg(&bvec[c0])     : 0.0f;
        float bz1 = (c0 + 1 < K3) ? __ldg(&bvec[c0 + 1]) : 0.0f;
        #pragma unroll
        for (int mt = 0; mt < 2; mt++) {
            d[mt][nt][0] = bz0; d[mt][nt][1] = bz1;
            d[mt][nt][2] = bz0; d[mt][nt][3] = bz1;
        }
    }
    #pragma unroll
    for (int ks = 0; ks < 8; ks++) {           // K = 64 in k8 steps
        uint32_t a[2][4];
        #pragma unroll
        for (int mt = 0; mt < 2; mt++) {
            int r0 = mtb + mt * 16 + g;
            a[mt][0] = f2tf32(sxt[r0    ][ks * 8 + tig]);
            a[mt][1] = f2tf32(sxt[r0 + 8][ks * 8 + tig]);
            a[mt][2] = f2tf32(sxt[r0    ][ks * 8 + tig + 4]);
            a[mt][3] = f2tf32(sxt[r0 + 8][ks * 8 + tig + 4]);
        }
        #pragma unroll
        for (int nt = 0; nt < NT; nt++) {
            int n0 = nt * 8 + g;
            uint32_t b[2];
            b[0] = f2tf32((n0 < K3) ? __ldg(&W[(ks * 8 + tig    ) * K3 + n0]) : 0.0f);
            b[1] = f2tf32((n0 < K3) ? __ldg(&W[(ks * 8 + tig + 4) * K3 + n0]) : 0.0f);
            mma_tf32(d[0][nt], a[0], b);
            mma_tf32(d[1][nt], a[1], b);
        }
    }
    #pragma unroll
    for (int mt = 0; mt < 2; mt++) {
        size_t r0 = btbase + mtb + mt * 16 + g;
        #pragma unroll
        for (int nt = 0; nt < NT; nt++) {
            int c0 = nt * 8 + 2 * tig;         // cols 150/151 are junk pad: ok
            *(float2*)&g_xp[r0 * XPP + c0]       = make_float2(d[mt][nt][0], d[mt][nt][1]);
            *(float2*)&g_xp[(r0 + 8) * XPP + c0] = make_float2(d[mt][nt][2], d[mt][nt][3]);
        }
    }
}

// ---------------- Phase 2: recurrence (hp only), fp32 exact -------------------
__global__ __launch_bounds__(NTHR, 2) void gru_recur_kernel(
    const float* __restrict__ U,    // [50, 150]
    const float* __restrict__ bvec, // [2, 150] (row 1 used here)
    const float* __restrict__ Wd,   // [50, 1]
    const float* __restrict__ bd,   // [1]
    float* __restrict__ out)        // [4096, 1]
{
    __shared__ __align__(16) float sh[BR * HP2];
    __shared__ float sgr[BR * NU];
    __shared__ float sz [BR * NU];

    const int tid  = threadIdx.x;
    const int k    = tid;
    const int brow = blockIdx.x * BR;

    for (int i = tid; i < BR * HP2; i += NTHR) sh[i] = 0.0f;

    u64 up[NU / 2];                 // U column k as packed f32x2 pairs (50 regs)
    u64 b1p = 0ull;
    if (k < K3) {
        b1p = pack2(__ldg(&bvec[K3 + k]), 0.0f);
        #pragma unroll
        for (int jg = 0; jg < NU / 2; jg++)
            up[jg] = pack2(__ldg(&U[(2 * jg) * K3 + k]),
                           __ldg(&U[(2 * jg + 1) * K3 + k]));
    }

    // prefetch XP for t = 0
    float xq[BR];
    if (k < K3) {
        #pragma unroll
        for (int r = 0; r < BR; r++)
            xq[r] = g_xp[((size_t)(brow + r) * TT) * XPP + k];
    }
    __syncthreads();                // sh init visible

    #pragma unroll 1
    for (int t = 0; t < TT; t++) {
        float xv[BR];
        #pragma unroll
        for (int r = 0; r < BR; r++) xv[r] = xq[r];
        if (t + 1 < TT && k < K3) {
            #pragma unroll
            for (int r = 0; r < BR; r++)
                xq[r] = g_xp[((size_t)(brow + r) * TT + t + 1) * XPP + k];
        }

        __syncthreads();            // (A) prev step's sh writes visible

        u64 acc[BR];
        #pragma unroll
        for (int r = 0; r < BR; r++) acc[r] = b1p;

        if (k < K3) {
            #pragma unroll
            for (int jg = 0; jg < 12; jg++) {
                const int j0 = jg * 4;
                #pragma unroll
                for (int r = 0; r < BR; r++) {
                    ulonglong2 hv = *(const ulonglong2*)(sh + r * HP2 + j0);
                    fma2(acc[r], hv.x, up[2 * jg],     acc[r]);
                    fma2(acc[r], hv.y, up[2 * jg + 1], acc[r]);
                }
            }
            #pragma unroll
            for (int r = 0; r < BR; r++) {     // tail j = 48,49
                u64 hv = *(const u64*)(sh + r * HP2 + 48);
                fma2(acc[r], hv, up[24], acc[r]);
            }
        }

        float aH[BR];               // hp (incl. b1); xv holds xp (incl. b0)
        #pragma unroll
        for (int r = 0; r < BR; r++) {
            float2 p = unpack2(acc[r]);
            aH[r] = p.x + p.y;
        }

        // gates: k<50 -> z; 50..99 -> r; 100..149 -> hcand + h update
        if (k < NU) {
            #pragma unroll
            for (int r = 0; r < BR; r++)
                sz[r * NU + k] = sigmoidf_(xv[r] + aH[r]);
        } else if (k < 2 * NU) {
            const int j = k - NU;
            #pragma unroll
            for (int r = 0; r < BR; r++)
                sgr[r * NU + j] = sigmoidf_(xv[r] + aH[r]);
        }
        __syncthreads();            // (B) sz/sgr ready; sh reads done

        if (k >= 2 * NU && k < K3) {
            const int j = k - 2 * NU;
            #pragma unroll
            for (int r = 0; r < BR; r++) {
                float hc   = fmaxf(xv[r] + sgr[r * NU + j] * aH[r], 0.0f);
                float zv   = sz[r * NU + j];
                float hold = sh[r * HP2 + j];
                sh[r * HP2 + j] = zv * hold + (1.0f - zv) * hc;
            }
        }
        // next iteration's barrier (A) orders these writes before reads
    }

    __syncthreads();                // final h visible
    if (tid < BR) {
        float acc = bd[0];
        #pragma unroll
        for (int j = 0; j < NU; j++)
            acc += sh[tid * HP2 + j] * __ldg(&Wd[j]);
        out[brow + tid] = acc;
    }
}

extern "C" void kernel_launch(void* const* d_in, const int* in_sizes, int n_in,
                              void* d_out, int out_size) {
    (void)in_sizes; (void)n_in; (void)out_size;
    const float* x    = (const float*)d_in[0];
    const float* W    = (const float*)d_in[1];
    const float* U    = (const float*)d_in[2];
    const float* bvec = (const float*)d_in[3];
    const float* Wd   = (const float*)d_in[4];
    const float* bd   = (const float*)d_in[5];
    float* out = (float*)d_out;

    xp_gemm_kernel<<<4096, 128>>>(x, W, bvec);
    gru_recur_kernel<<<4096 / BR, NTHR>>>(U, bvec, Wd, bd, out);
}

// round 14
// speedup vs baseline: 2.0136x; 1.0625x over previous
#include <cuda_runtime.h>
#include <cstdint>

// GRU split into two kernels (sm_103 base target — no tcgen05 on this toolchain):
//  Phase 1: XP = x.W + b0 for ALL (b,t) via tf32 mma.sync m16n8k8 (unchanged).
//  Phase 2: recurrence hp = h.U + b1, fp32 f32x2 SIMT.
//    R13 change: BR 16->8, grid 512, __launch_bounds__(160,4) -> occ 4,
//    one wave (592 slots >= 512 CTAs), 17.3 warps/SM for latency hiding.
// [R14: identical to R13 — R13 bench died in the GB300 container broker
//  before compiling/running; resubmitting for a clean measurement.]

#define TT   128
#define FF   64
#define NU   50
#define K3   150
#define XPP  152                   // XP row pitch (floats)
#define BTN  (4096 * 128)          // total bt rows
#define BR   8
#define NTHR 160
#define HP2  52                    // h row pitch
#define NT   19                    // phase-1 n8 tiles (152 cols)

__device__ float g_xp[(size_t)BTN * XPP];   // 319 MB scratch (static device mem)

typedef unsigned long long u64;

__device__ __forceinline__ void fma2(u64& d, u64 a, u64 b, u64 c) {
    asm("fma.rn.f32x2 %0, %1, %2, %3;" : "=l"(d) : "l"(a), "l"(b), "l"(c));
}
__device__ __forceinline__ u64 pack2(float lo, float hi) {
    u64 r; asm("mov.b64 %0, {%1, %2};" : "=l"(r) : "f"(lo), "f"(hi)); return r;
}
__device__ __forceinline__ float2 unpack2(u64 v) {
    float2 r; asm("mov.b64 {%0, %1}, %2;" : "=f"(r.x), "=f"(r.y) : "l"(v)); return r;
}
__device__ __forceinline__ float sigmoidf_(float v) {
    return __fdividef(1.0f, 1.0f + __expf(-v));
}
__device__ __forceinline__ uint32_t f2tf32(float f) {
    uint32_t r; asm("cvt.rna.tf32.f32 %0, %1;" : "=r"(r) : "f"(f)); return r;
}
__device__ __forceinline__ void mma_tf32(float* d, const uint32_t* a,
                                         const uint32_t* b) {
    asm volatile(
        "mma.sync.aligned.m16n8k8.row.col.f32.tf32.tf32.f32 "
        "{%0,%1,%2,%3}, {%4,%5,%6,%7}, {%8,%9}, {%0,%1,%2,%3};"
        : "+f"(d[0]), "+f"(d[1]), "+f"(d[2]), "+f"(d[3])
        : "r"(a[0]), "r"(a[1]), "r"(a[2]), "r"(a[3]), "r"(b[0]), "r"(b[1]));
}

// ---------------- Phase 1: XP[bt][152] = x[bt][64] . W[64][150] + b0 ----------
// grid 4096 (one CTA = one batch row's 128 timesteps), block 128 (4 warps x m32).
__global__ __launch_bounds__(128, 2) void xp_gemm_kernel(
    const float* __restrict__ x,    // [BTN, 64]
    const float* __restrict__ W,    // [64, 150]
    const float* __restrict__ bvec) // [2, 150] (row 0 used here)
{
    __shared__ float sxt[128][68];  // x tile, padded pitch
    const int tid = threadIdx.x, warp = tid >> 5, lane = tid & 31;
    const int g = lane >> 2, tig = lane & 3;
    const size_t btbase = (size_t)blockIdx.x * 128;

    for (int i = tid; i < 128 * FF; i += 128) {
        int r = i >> 6, f = i & 63;
        sxt[r][f] = x[(btbase + r) * FF + f];
    }
    __syncthreads();

    const int mtb = warp * 32;      // warp covers rows [mtb, mtb+32)
    float d[2][NT][4];
    #pragma unroll
    for (int nt = 0; nt < NT; nt++) {          // init D with bias b0
        int c0 = nt * 8 + 2 * tig;
        float bz0 = (c0     < K3) ? __ldg(&bvec[c0])     : 0.0f;
        float bz1 = (c0 + 1 < K3) ? __ldg(&bvec[c0 + 1]) : 0.0f;
        #pragma unroll
        for (int mt = 0; mt < 2; mt++) {
            d[mt][nt][0] = bz0; d[mt][nt][1] = bz1;
            d[mt][nt][2] = bz0; d[mt][nt][3] = bz1;
        }
    }
    #pragma unroll
    for (int ks = 0; ks < 8; ks++) {           // K = 64 in k8 steps
        uint32_t a[2][4];
        #pragma unroll
        for (int mt = 0; mt < 2; mt++) {
            int r0 = mtb + mt * 16 + g;
            a[mt][0] = f2tf32(sxt[r0    ][ks * 8 + tig]);
            a[mt][1] = f2tf32(sxt[r0 + 8][ks * 8 + tig]);
            a[mt][2] = f2tf32(sxt[r0    ][ks * 8 + tig + 4]);
            a[mt][3] = f2tf32(sxt[r0 + 8][ks * 8 + tig + 4]);
        }
        #pragma unroll
        for (int nt = 0; nt < NT; nt++) {
            int n0 = nt * 8 + g;
            uint32_t b[2];
            b[0] = f2tf32((n0 < K3) ? __ldg(&W[(ks * 8 + tig    ) * K3 + n0]) : 0.0f);
            b[1] = f2tf32((n0 < K3) ? __ldg(&W[(ks * 8 + tig + 4) * K3 + n0]) : 0.0f);
            mma_tf32(d[0][nt], a[0], b);
            mma_tf32(d[1][nt], a[1], b);
        }
    }
    #pragma unroll
    for (int mt = 0; mt < 2; mt++) {
        size_t r0 = btbase + mtb + mt * 16 + g;
        #pragma unroll
        for (int nt = 0; nt < NT; nt++) {
            int c0 = nt * 8 + 2 * tig;         // cols 150/151 are junk pad: ok
            *(float2*)&g_xp[r0 * XPP + c0]       = make_float2(d[mt][nt][0], d[mt][nt][1]);
            *(float2*)&g_xp[(r0 + 8) * XPP + c0] = make_float2(d[mt][nt][2], d[mt][nt][3]);
        }
    }
}

// ---------------- Phase 2: recurrence (hp only), fp32 exact -------------------
// grid 512 x 8 rows, occ 4 (regs capped at 102) -> one wave, 17.3 warps/SM.
__global__ __launch_bounds__(NTHR, 4) void gru_recur_kernel(
    const float* __restrict__ U,    // [50, 150]
    const float* __restrict__ bvec, // [2, 150] (row 1 used here)
    const float* __restrict__ Wd,   // [50, 1]
    const float* __restrict__ bd,   // [1]
    float* __restrict__ out)        // [4096, 1]
{
    __shared__ __align__(16) float sh[BR * HP2];
    __shared__ float sgr[BR * NU];
    __shared__ float sz [BR * NU];

    const int tid  = threadIdx.x;
    const int k    = tid;
    const int brow = blockIdx.x * BR;

    for (int i = tid; i < BR * HP2; i += NTHR) sh[i] = 0.0f;

    u64 up[NU / 2];                 // U column k as packed f32x2 pairs (50 regs)
    u64 b1p = 0ull;
    if (k < K3) {
        b1p = pack2(__ldg(&bvec[K3 + k]), 0.0f);
        #pragma unroll
        for (int jg = 0; jg < NU / 2; jg++)
            up[jg] = pack2(__ldg(&U[(2 * jg) * K3 + k]),
                           __ldg(&U[(2 * jg + 1) * K3 + k]));
    }

    // prefetch XP for t = 0
    float xq[BR];
    if (k < K3) {
        #pragma unroll
        for (int r = 0; r < BR; r++)
            xq[r] = g_xp[((size_t)(brow + r) * TT) * XPP + k];
    }
    __syncthreads();                // sh init visible

    #pragma unroll 1
    for (int t = 0; t < TT; t++) {
        float xv[BR];
        #pragma unroll
        for (int r = 0; r < BR; r++) xv[r] = xq[r];
        if (t + 1 < TT && k < K3) {
            #pragma unroll
            for (int r = 0; r < BR; r++)
                xq[r] = g_xp[((size_t)(brow + r) * TT + t + 1) * XPP + k];
        }

        __syncthreads();            // (A) prev step's sh writes visible

        u64 acc[BR];
        #pragma unroll
        for (int r = 0; r < BR; r++) acc[r] = b1p;

        if (k < K3) {
            #pragma unroll
            for (int jg = 0; jg < 12; jg++) {
                const int j0 = jg * 4;
                #pragma unroll
                for (int r = 0; r < BR; r++) {
                    ulonglong2 hv = *(const ulonglong2*)(sh + r * HP2 + j0);
                    fma2(acc[r], hv.x, up[2 * jg],     acc[r]);
                    fma2(acc[r], hv.y, up[2 * jg + 1], acc[r]);
                }
            }
            #pragma unroll
            for (int r = 0; r < BR; r++) {     // tail j = 48,49
                u64 hv = *(const u64*)(sh + r * HP2 + 48);
                fma2(acc[r], hv, up[24], acc[r]);
            }
        }

        float aH[BR];               // hp (incl. b1); xv holds xp (incl. b0)
        #pragma unroll
        for (int r = 0; r < BR; r++) {
            float2 p = unpack2(acc[r]);
            aH[r] = p.x + p.y;
        }

        // gates: k<50 -> z; 50..99 -> r; 100..149 -> hcand + h update
        if (k < NU) {
            #pragma unroll
            for (int r = 0; r < BR; r++)
                sz[r * NU + k] = sigmoidf_(xv[r] + aH[r]);
        } else if (k < 2 * NU) {
            const int j = k - NU;
            #pragma unroll
            for (int r = 0; r < BR; r++)
                sgr[r * NU + j] = sigmoidf_(xv[r] + aH[r]);
        }
        __syncthreads();            // (B) sz/sgr ready; sh reads done

        if (k >= 2 * NU && k < K3) {
            const int j = k - 2 * NU;
            #pragma unroll
            for (int r = 0; r < BR; r++) {
                float hc   = fmaxf(xv[r] + sgr[r * NU + j] * aH[r], 0.0f);
                float zv   = sz[r * NU + j];
                float hold = sh[r * HP2 + j];
                sh[r * HP2 + j] = zv * hold + (1.0f - zv) * hc;
            }
        }
        // next iteration's barrier (A) orders these writes before reads
    }

    __syncthreads();                // final h visible
    if (tid < BR) {
        float acc = bd[0];
        #pragma unroll
        for (int j = 0; j < NU; j++)
            acc += sh[tid * HP2 + j] * __ldg(&Wd[j]);
        out[brow + tid] = acc;
    }
}

extern "C" void kernel_launch(void* const* d_in, const int* in_sizes, int n_in,
                              void* d_out, int out_size) {
    (void)in_sizes; (void)n_in; (void)out_size;
    const float* x    = (const float*)d_in[0];
    const float* W    = (const float*)d_in[1];
    const float* U    = (const float*)d_in[2];
    const float* bvec = (const float*)d_in[3];
    const float* Wd   = (const float*)d_in[4];
    const float* bd   = (const float*)d_in[5];
    float* out = (float*)d_out;

    xp_gemm_kernel<<<4096, 128>>>(x, W, bvec);
    gru_recur_kernel<<<4096 / BR, NTHR>>>(U, bvec, Wd, bd, out);
}

// round 17
// speedup vs baseline: 2.6357x; 1.3090x over previous
#include <cuda_runtime.h>
#include <cuda_bf16.h>
#include <cstdint>

// GRU, two kernels (sm_103 base target):
//  Phase 1: XP = x.W + b0 via tf32 mma.sync m16n8k8. R15: W pre-converted to
//           tf32 and staged in dynamic SMEM (kills 304 in-loop LDG+cvt/warp).
//  Phase 2: recurrence on tensor cores: hp = h.U + b1 via bf16 m16n8k16
//           mma.sync, 3-product hi/lo split (err ~8e-6). 16 rows/CTA, 5 warps
//           x 32 cols. Epilogue = 800 (r,j) gate tasks over all 160 threads.

#define TT   128
#define FF   64
#define NU   50
#define K3   150
#define XPP  152
#define BTN  (4096 * 128)
#define NT   19

__device__ float g_xp[(size_t)BTN * XPP];   // 319 MB scratch

__device__ __forceinline__ float sigmoidf_(float v) {
    return __fdividef(1.0f, 1.0f + __expf(-v));
}
__device__ __forceinline__ uint32_t f2tf32(float f) {
    uint32_t r; asm("cvt.rna.tf32.f32 %0, %1;" : "=r"(r) : "f"(f)); return r;
}
__device__ __forceinline__ void mma_tf32(float* d, const uint32_t* a,
                                         const uint32_t* b) {
    asm volatile(
        "mma.sync.aligned.m16n8k8.row.col.f32.tf32.tf32.f32 "
        "{%0,%1,%2,%3}, {%4,%5,%6,%7}, {%8,%9}, {%0,%1,%2,%3};"
        : "+f"(d[0]), "+f"(d[1]), "+f"(d[2]), "+f"(d[3])
        : "r"(a[0]), "r"(a[1]), "r"(a[2]), "r"(a[3]), "r"(b[0]), "r"(b[1]));
}
__device__ __forceinline__ void mma_bf16(float* d, const uint32_t* a,
                                         const uint32_t* b) {
    asm volatile(
        "mma.sync.aligned.m16n8k16.row.col.f32.bf16.bf16.f32 "
        "{%0,%1,%2,%3}, {%4,%5,%6,%7}, {%8,%9}, {%0,%1,%2,%3};"
        : "+f"(d[0]), "+f"(d[1]), "+f"(d[2]), "+f"(d[3])
        : "r"(a[0]), "r"(a[1]), "r"(a[2]), "r"(a[3]), "r"(b[0]), "r"(b[1]));
}
__device__ __forceinline__ uint16_t bfbits(__nv_bfloat16 h) {
    return *reinterpret_cast<uint16_t*>(&h);
}

// ---------------- Phase 1: XP[bt][152] = x[bt][64] . W[64][150] + b0 ----------
#define P1_SXP 68
#define P1_WSP 168
#define P1_SMEM ((128 * P1_SXP + 64 * P1_WSP) * 4)

__global__ __launch_bounds__(128, 2) void xp_gemm_kernel(
    const float* __restrict__ x,
    const float* __restrict__ W,
    const float* __restrict__ bvec)
{
    extern __shared__ float dsm[];
    float* sxt = dsm;                    // [128][68] x tile, tf32-pre-rounded
    float* ws  = dsm + 128 * P1_SXP;     // [64][168] W, tf32-pre-rounded

    const int tid = threadIdx.x, warp = tid >> 5, lane = tid & 31;
    const int g = lane >> 2, tig = lane & 3;
    const size_t btbase = (size_t)blockIdx.x * 128;

    for (int i = tid; i < 128 * FF; i += 128) {
        int r = i >> 6, f = i & 63;
        sxt[r * P1_SXP + f] =
            __uint_as_float(f2tf32(x[(btbase + r) * FF + f]));
    }
    for (int i = tid; i < 64 * P1_WSP; i += 128) {
        int k = i / P1_WSP, n = i % P1_WSP;
        float v = (n < K3) ? __ldg(&W[k * K3 + n]) : 0.0f;
        ws[i] = __uint_as_float(f2tf32(v));
    }
    __syncthreads();

    const int mtb = warp * 32;
    float d[2][NT][4];
    #pragma unroll
    for (int nt = 0; nt < NT; nt++) {
        int c0 = nt * 8 + 2 * tig;
        float bz0 = (c0     < K3) ? __ldg(&bvec[c0])     : 0.0f;
        float bz1 = (c0 + 1 < K3) ? __ldg(&bvec[c0 + 1]) : 0.0f;
        #pragma unroll
        for (int mt = 0; mt < 2; mt++) {
            d[mt][nt][0] = bz0; d[mt][nt][1] = bz1;
            d[mt][nt][2] = bz0; d[mt][nt][3] = bz1;
        }
    }
    #pragma unroll
    for (int ks = 0; ks < 8; ks++) {
        uint32_t a[2][4];
        #pragma unroll
        for (int mt = 0; mt < 2; mt++) {
            int r0 = mtb + mt * 16 + g;
            a[mt][0] = __float_as_uint(sxt[ r0      * P1_SXP + ks * 8 + tig]);
            a[mt][1] = __float_as_uint(sxt[(r0 + 8) * P1_SXP + ks * 8 + tig]);
            a[mt][2] = __float_as_uint(sxt[ r0      * P1_SXP + ks * 8 + tig + 4]);
            a[mt][3] = __float_as_uint(sxt[(r0 + 8) * P1_SXP + ks * 8 + tig + 4]);
        }
        #pragma unroll
        for (int nt = 0; nt < NT; nt++) {
            int n0 = nt * 8 + g;
            uint32_t b[2];
            b[0] = __float_as_uint(ws[(ks * 8 + tig    ) * P1_WSP + n0]);
            b[1] = __float_as_uint(ws[(ks * 8 + tig + 4) * P1_WSP + n0]);
            mma_tf32(d[0][nt], a[0], b);
            mma_tf32(d[1][nt], a[1], b);
        }
    }
    #pragma unroll
    for (int mt = 0; mt < 2; mt++) {
        size_t r0 = btbase + mtb + mt * 16 + g;
        #pragma unroll
        for (int nt = 0; nt < NT; nt++) {
            int c0 = nt * 8 + 2 * tig;
            *(float2*)&g_xp[r0 * XPP + c0]       = make_float2(d[mt][nt][0], d[mt][nt][1]);
            *(float2*)&g_xp[(r0 + 8) * XPP + c0] = make_float2(d[mt][nt][2], d[mt][nt][3]);
        }
    }
}

// ---------------- Phase 2: recurrence on bf16 tensor cores -------------------
// CTA: 16 rows, 160 threads (5 warps x 32 cols). Per step:
//   hp[16x160] = h[16x64(bf16 hi/lo)] . U[64x160] + b1   (3-product bf16 MMA)
// then 800 (r,j) gate tasks across all threads update h (fp32 + bf16 hi/lo).
#define BR2   16
#define NTHR2 160
#define HPX   164     // hp pitch (floats)
#define HFP   52      // fp32 h pitch
#define HBP   36      // bf16-pair h pitch (u32 words) => 72 bf16/row

__global__ __launch_bounds__(NTHR2, 2) void gru_recur_kernel(
    const float* __restrict__ U,    // [50,150]
    const float* __restrict__ bvec, // [2,150]
    const float* __restrict__ Wd,   // [50,1]
    const float* __restrict__ bd,   // [1]
    float* __restrict__ out)        // [4096,1]
{
    __shared__ float    s_f [BR2 * HFP];    // exact fp32 h
    __shared__ uint32_t s_hi[BR2 * HBP];    // bf16 hi pairs (k-major pairs)
    __shared__ uint32_t s_lo[BR2 * HBP];    // bf16 lo pairs
    __shared__ float    s_hp[BR2 * HPX];    // hp exchange

    const int tid  = threadIdx.x;
    const int warp = tid >> 5, lane = tid & 31;
    const int g = lane >> 2, tig = lane & 3;
    const int wslab = warp * 32;            // this warp's 32 output cols
    const int brow = blockIdx.x * BR2;

    // init h = 0 (both representations; padded k 50..63 stay 0 forever)
    for (int i = tid; i < BR2 * HFP; i += NTHR2) s_f[i] = 0.0f;
    for (int i = tid; i < BR2 * HBP; i += NTHR2) { s_hi[i] = 0u; s_lo[i] = 0u; }

    // ---- static B fragments: U split into bf16 hi/lo, reg-resident ----
    uint32_t bh[4][4][2], bl[4][4][2];
    #pragma unroll
    for (int ks = 0; ks < 4; ks++)
        #pragma unroll
        for (int nt = 0; nt < 4; nt++) {
            int n = wslab + nt * 8 + g;
            #pragma unroll
            for (int hf = 0; hf < 2; hf++) {
                int k0 = ks * 16 + 2 * tig + hf * 8;
                float u0 = (k0     < NU && n < K3) ? __ldg(&U[ k0      * K3 + n]) : 0.0f;
                float u1 = (k0 + 1 < NU && n < K3) ? __ldg(&U[(k0 + 1) * K3 + n]) : 0.0f;
                __nv_bfloat16 h0 = __float2bfloat16(u0);
                __nv_bfloat16 h1 = __float2bfloat16(u1);
                float r0 = u0 - __bfloat162float(h0);
                float r1 = u1 - __bfloat162float(h1);
                bh[ks][nt][hf] = (uint32_t)bfbits(h0) | ((uint32_t)bfbits(h1) << 16);
                bl[ks][nt][hf] = (uint32_t)bfbits(__float2bfloat16(r0))
                               | ((uint32_t)bfbits(__float2bfloat16(r1)) << 16);
            }
        }

    // bias b1 for D init (per nt, cols 2tig, 2tig+1)
    float bz0[4], bz1[4];
    #pragma unroll
    for (int nt = 0; nt < 4; nt++) {
        int c0 = wslab + nt * 8 + 2 * tig;
        bz0[nt] = (c0     < K3) ? __ldg(&bvec[K3 + c0])     : 0.0f;
        bz1[nt] = (c0 + 1 < K3) ? __ldg(&bvec[K3 + c0 + 1]) : 0.0f;
    }

    // ---- epilogue task mapping: 800 tasks = 160 thr x 5 ----
    int ofsP[5], ofsF[5], ofsB[5];
    const float* p[5];
    #pragma unroll
    for (int i = 0; i < 5; i++) {
        int task = tid + i * NTHR2;
        int r = task / NU, j = task - r * NU;
        ofsP[i] = r * HPX + j;
        ofsF[i] = r * HFP + j;
        ofsB[i] = r * (HBP * 2) + j;        // bf16 element index
        p[i] = g_xp + ((size_t)(brow + r) * TT) * XPP + j;
    }

    // prefetch xp for t = 0
    float xq[15];
    #pragma unroll
    for (int i = 0; i < 5; i++) {
        xq[3*i]   = __ldg(p[i]);
        xq[3*i+1] = __ldg(p[i] + 50);
        xq[3*i+2] = __ldg(p[i] + 100);
        p[i] += XPP;
    }

    __nv_bfloat16* s_hib = (__nv_bfloat16*)s_hi;
    __nv_bfloat16* s_lob = (__nv_bfloat16*)s_lo;

    #pragma unroll 1
    for (int t = 0; t < TT; t++) {
        __syncthreads();   // (A) prev epilogue's h writes + hp reads done

        float xv[15];
        #pragma unroll
        for (int i = 0; i < 15; i++) xv[i] = xq[i];
        if (t + 1 < TT) {
            #pragma unroll
            for (int i = 0; i < 5; i++) {
                xq[3*i]   = __ldg(p[i]);
                xq[3*i+1] = __ldg(p[i] + 50);
                xq[3*i+2] = __ldg(p[i] + 100);
                p[i] += XPP;
            }
        }

        // ---- MMA: hp = h.U + b1 ----
        float d[4][4];
        #pragma unroll
        for (int nt = 0; nt < 4; nt++) {
            d[nt][0] = bz0[nt]; d[nt][1] = bz1[nt];
            d[nt][2] = bz0[nt]; d[nt][3] = bz1[nt];
        }
        #pragma unroll
        for (int ks = 0; ks < 4; ks++) {
            const int w0 = ks * 8 + tig;
            uint32_t ah[4], al[4];
            ah[0] = s_hi[ g      * HBP + w0];
            ah[1] = s_hi[(g + 8) * HBP + w0];
            ah[2] = s_hi[ g      * HBP + w0 + 4];
            ah[3] = s_hi[(g + 8) * HBP + w0 + 4];
            al[0] = s_lo[ g      * HBP + w0];
            al[1] = s_lo[(g + 8) * HBP + w0];
            al[2] = s_lo[ g      * HBP + w0 + 4];
            al[3] = s_lo[(g + 8) * HBP + w0 + 4];
            #pragma unroll
            for (int nt = 0; nt < 4; nt++) {
                mma_bf16(d[nt], ah, bh[ks][nt]);
                mma_bf16(d[nt], al, bh[ks][nt]);
                mma_bf16(d[nt], ah, bl[ks][nt]);
            }
        }
        #pragma unroll
        for (int nt = 0; nt < 4; nt++) {
            int c0 = wslab + nt * 8 + 2 * tig;
            *(float2*)&s_hp[ g      * HPX + c0] = make_float2(d[nt][0], d[nt][1]);
            *(float2*)&s_hp[(g + 8) * HPX + c0] = make_float2(d[nt][2], d[nt][3]);
        }
        __syncthreads();   // (B) hp visible

        // ---- epilogue: gates + h update ----
        #pragma unroll
        for (int i = 0; i < 5; i++) {
            float hz = s_hp[ofsP[i]];
            float hr = s_hp[ofsP[i] + 50];
            float hh = s_hp[ofsP[i] + 100];
            float z  = sigmoidf_(xv[3*i]     + hz);
            float rg = sigmoidf_(xv[3*i + 1] + hr);
            float hc = fmaxf(xv[3*i + 2] + rg * hh, 0.0f);
            float hold = s_f[ofsF[i]];
            float hn = z * hold + (1.0f - z) * hc;
            s_f[ofsF[i]] = hn;
            __nv_bfloat16 hb = __float2bfloat16(hn);
            float rem = hn - __bfloat162float(hb);
            s_hib[ofsB[i]] = hb;
            s_lob[ofsB[i]] = __float2bfloat16(rem);
        }
    }

    __syncthreads();       // final h visible
    if (tid < BR2) {
        float acc = bd[0];
        #pragma unroll
        for (int j = 0; j < NU; j++)
            acc += s_f[tid * HFP + j] * __ldg(&Wd[j]);
        out[brow + tid] = acc;
    }
}

extern "C" void kernel_launch(void* const* d_in, const int* in_sizes, int n_in,
                              void* d_out, int out_size) {
    (void)in_sizes; (void)n_in; (void)out_size;
    const float* x    = (const float*)d_in[0];
    const float* W    = (const float*)d_in[1];
    const float* U    = (const float*)d_in[2];
    const float* bvec = (const float*)d_in[3];
    const float* Wd   = (const float*)d_in[4];
    const float* bd   = (const float*)d_in[5];
    float* out = (float*)d_out;

    static bool attr_set = false;
    if (!attr_set) {
        cudaFuncSetAttribute(xp_gemm_kernel,
                             cudaFuncAttributeMaxDynamicSharedMemorySize,
                             P1_SMEM);
        attr_set = true;
    }
    xp_gemm_kernel<<<4096, 128, P1_SMEM>>>(x, W, bvec);
    gru_recur_kernel<<<4096 / BR2, NTHR2>>>(U, bvec, Wd, bd, out);
}